// round 16
// baseline (speedup 1.0000x reference)
#include <cuda_runtime.h>
#include <cuda_fp16.h>
#include <cstdint>
#include <cstddef>

#define SEQ 2048
#define BATCH 64
#define NBLK 128
#define NTHR 512
#define UNITS 4
#define LOSC 2048.0f
#define AROW 520      // halves per A row (1040B, ≡16 mod 128 -> ldmatrix conflict-free)
#define WROW 1032     // halves per W row (2064B, ≡16 mod 128)
#define PST  20

#define SB_WH 0                 // Whi [16][WROW] half
#define SB_WL 33024             // Wlo
#define SB_AX 66048             // x tile [64][AROW] half
#define SB_AH 132608            // h tile
#define SB_PX 199168            // psm_x [2][64][PST] f32
#define SB_PH 209408            // psm_h [64][PST] f32
#define SB_BS 214528            // bias [16] f32
#define SMEM_BYTES 214784

__device__ float    g_h[2][BATCH * 512];
__device__ unsigned g_ctr;
__device__ unsigned g_done;

__device__ __forceinline__ float fsig(float x)  { return 1.0f/(1.0f+__expf(-x)); }
__device__ __forceinline__ float ftanh(float x) { float e=__expf(2.0f*x); return 1.0f-2.0f/(e+1.0f); }
__device__ __forceinline__ unsigned ld_acq(const unsigned* p){
    unsigned v; asm volatile("ld.acquire.gpu.global.u32 %0,[%1];":"=r"(v):"l"(p):"memory"); return v;
}
__device__ __forceinline__ void red_rel(unsigned* p){
    asm volatile("red.release.gpu.global.add.u32 [%0],%1;"::"l"(p),"r"(1u):"memory");
}
__device__ __forceinline__ void stcs4(float* p, float4 v){
    asm volatile("st.global.cs.v4.f32 [%0],{%1,%2,%3,%4};"
                 ::"l"(p),"f"(v.x),"f"(v.y),"f"(v.z),"f"(v.w));
}
__device__ __forceinline__ void barx(int id,int cnt){
    asm volatile("bar.sync %0,%1;"::"r"(id),"r"(cnt):"memory");
}
__device__ __forceinline__ float4 ldcg4(const float* p){
    float4 v; asm volatile("ld.global.cg.v4.f32 {%0,%1,%2,%3},[%4];"
        :"=f"(v.x),"=f"(v.y),"=f"(v.z),"=f"(v.w):"l"(p)); return v;
}
__device__ __forceinline__ uint32_t ph2(float a,float b){
    __half2 h=__floats2half2_rn(a,b); return *(uint32_t*)&h;
}
__device__ __forceinline__ void ldsm4(uint32_t* r, uint32_t a){
    asm volatile("ldmatrix.sync.aligned.m8n8.x4.shared.b16 {%0,%1,%2,%3},[%4];"
        :"=r"(r[0]),"=r"(r[1]),"=r"(r[2]),"=r"(r[3]):"r"(a));
}
__device__ __forceinline__ void ldsm2(uint32_t* r, uint32_t a){
    asm volatile("ldmatrix.sync.aligned.m8n8.x2.shared.b16 {%0,%1},[%2];"
        :"=r"(r[0]),"=r"(r[1]):"r"(a));
}
__device__ __forceinline__ void mma16816(float* c, const uint32_t* a, const uint32_t* b){
    asm volatile("mma.sync.aligned.m16n8k16.row.col.f32.f16.f16.f32 "
        "{%0,%1,%2,%3},{%4,%5,%6,%7},{%8,%9},{%0,%1,%2,%3};"
        :"+f"(c[0]),"+f"(c[1]),"+f"(c[2]),"+f"(c[3])
        :"r"(a[0]),"r"(a[1]),"r"(a[2]),"r"(a[3]),"r"(b[0]),"r"(b[1]));
}

// fp32[64][512] (global) -> fp16 tile [64][AROW] (smem). 512 threads. cg loads.
__device__ __forceinline__ void conv_tile(uint32_t dst, const float* src, int tid){
    int row=tid>>3, c8=tid&7;
    const float* s = src + (size_t)row*512 + c8*8;
    uint32_t d = dst + (uint32_t)(row*AROW + c8*8)*2;
    #pragma unroll
    for(int i=0;i<8;++i){
        float4 v0=ldcg4(s+i*64), v1=ldcg4(s+i*64+4);
        uint32_t h0=ph2(v0.x,v0.y),h1=ph2(v0.z,v0.w),h2=ph2(v1.x,v1.y),h3=ph2(v1.z,v1.w);
        asm volatile("st.shared.v4.b32 [%0],{%1,%2,%3,%4};"
            ::"r"(d+i*128),"r"(h0),"r"(h1),"r"(h2),"r"(h3));
    }
}
// same but 256 threads (x-warps), plain loads
__device__ __forceinline__ void conv_x256(uint32_t dst, const float* src, int tid){
    int row=tid>>2, c4=tid&3;
    const float* s = src + (size_t)row*512 + c4*8;
    uint32_t d = dst + (uint32_t)(row*AROW + c4*8)*2;
    #pragma unroll
    for(int i=0;i<16;++i){
        float4 v0=*(const float4*)(s+i*32), v1=*(const float4*)(s+i*32+4);
        uint32_t h0=ph2(v0.x,v0.y),h1=ph2(v0.z,v0.w),h2=ph2(v1.x,v1.y),h3=ph2(v1.z,v1.w);
        asm volatile("st.shared.v4.b32 [%0],{%1,%2,%3,%4};"
            ::"r"(d+i*64),"r"(h0),"r"(h1),"r"(h2),"r"(h3));
    }
}
// K=512 half-GEMM: 32 k-steps of m16n8k16, hi+lo accumulators
__device__ __forceinline__ void gemm_half(uint32_t ab, uint32_t wh, uint32_t wl,
                                          int mtile,int ntile,int lane,
                                          float* ch,float* cl){
    uint32_t aa = ab + (uint32_t)((mtile*16+(lane&7)+((lane>>3)&1)*8)*AROW
                                  + ((lane>>4)&1)*8)*2;
    int bl=lane&15;
    uint32_t wo = (uint32_t)((ntile*8+(bl&7))*WROW + ((bl>>3)&1)*8)*2;
    uint32_t bh=wh+wo, blo=wl+wo;
    #pragma unroll
    for(int kq=0;kq<32;++kq){
        uint32_t a[4],b0[2],b1[2];
        ldsm4(a, aa+kq*32);
        ldsm2(b0, bh+kq*32);
        ldsm2(b1, blo+kq*32);
        mma16816(ch,a,b0);
        mma16816(cl,a,b1);
    }
}
__device__ __forceinline__ void put_psm(float* P,int mtile,int ntile,int lane,
                                        const float* ch,const float* cl){
    int r=mtile*16+(lane>>2), c=ntile*8+2*(lane&3);
    P[r*PST+c]       = ch[0]+cl[0]*(1.0f/LOSC);
    P[r*PST+c+1]     = ch[1]+cl[1]*(1.0f/LOSC);
    P[(r+8)*PST+c]   = ch[2]+cl[2]*(1.0f/LOSC);
    P[(r+8)*PST+c+1] = ch[3]+cl[3]*(1.0f/LOSC);
}

__global__ void __launch_bounds__(NTHR,1)
lstm_kernel(const float* __restrict__ x,
            const float* __restrict__ Wf_,const float* __restrict__ bf_,
            const float* __restrict__ Wi_,const float* __restrict__ bi_,
            const float* __restrict__ Wg_,const float* __restrict__ bg_,
            const float* __restrict__ Wo_,const float* __restrict__ bo_,
            float* __restrict__ out)
{
    extern __shared__ char sm[];
    const int tid=threadIdx.x, bid=blockIdx.x, j0=bid*UNITS;
    const int wid=tid>>5, lane=tid&31;
    const uint32_t smb=(uint32_t)__cvta_generic_to_shared(sm);
    float* bsm=(float*)(sm+SB_BS);
    float* pxm=(float*)(sm+SB_PX);
    float* phm=(float*)(sm+SB_PH);

    // ---- init: W hi/lo fp16, bias, h0 zero, x0 tile ----
    {
        const float* Wp[4]={Wf_,Wi_,Wg_,Wo_};
        for(int j=tid;j<16*1024;j+=NTHR){
            int r=j>>10,k=j&1023, u=r>>2,g=r&3;
            float w=Wp[g][(size_t)(j0+u)*1024+k];
            __half hi=__float2half_rn(w);
            __half lo=__float2half_rn((w-__half2float(hi))*LOSC);
            *(__half*)(sm+SB_WH+(r*WROW+k)*2)=hi;
            *(__half*)(sm+SB_WL+(r*WROW+k)*2)=lo;
        }
        if(tid<16){ int u=tid>>2,g=tid&3;
            const float* bp=(g==0)?bf_:(g==1)?bi_:(g==2)?bg_:bo_;
            bsm[tid]=bp[j0+u]; }
        if(tid<64){
            *(float4*)&g_h[0][(size_t)tid*512+j0]=make_float4(0.f,0.f,0.f,0.f);
            __threadfence();
        }
        conv_tile(smb+SB_AX, x, tid);      // x_0
    }
    __syncthreads();
    if(tid==0) red_rel(&g_ctr);            // h0 visible

    const int cw=(wid<8)?wid:wid-8;
    const int mtile=cw>>1, ntile=cw&1;

    float br[16], c0=0.f,c1=0.f,c2=0.f,c3=0.f;
    if(wid>=14){ 
        #pragma unroll
        for(int r=0;r<16;++r) br[r]=bsm[r]; 
    }

    for(int t=0;t<SEQ;++t){
        const int par=t&1;
        float ch[4]={0,0,0,0}, cl[4]={0,0,0,0};

        if(wid<8){                                   // x-half GEMM (no h dep)
            gemm_half(smb+SB_AX, smb+SB_WH, smb+SB_WL, mtile,ntile,lane, ch,cl);
            put_psm(pxm+par*64*PST, mtile,ntile,lane, ch,cl);
        } else if(wid==8){                           // observe h_{t-1} global
            const unsigned tgt=(unsigned)(t+1)*NBLK;
            while(ld_acq(&g_ctr)<tgt){}
        }
        barx(1,NTHR);                                // psm_x done + observed

        conv_tile(smb+SB_AH, g_h[par], tid);         // h -> fp16 tile (all threads)
        barx(2,NTHR);

        if(wid>=8){                                  // h-half GEMM (critical)
            ch[0]=ch[1]=ch[2]=ch[3]=0.f; cl[0]=cl[1]=cl[2]=cl[3]=0.f;
            gemm_half(smb+SB_AH, smb+SB_WH+1024, smb+SB_WL+1024,
                      mtile,ntile,lane, ch,cl);
            put_psm(phm, mtile,ntile,lane, ch,cl);
        } else if(t+1<SEQ){                          // next x tile in shadow
            conv_x256(smb+SB_AX, x+(size_t)(t+1)*BATCH*512, tid);
        }
        barx(3,NTHR);                                // psm_h + x tile ready

        if(wid>=14){                                 // epilogue: 64 threads
            const int b=(wid-14)*32+lane;
            float pre[16];
            const float4* p1=(const float4*)(pxm+par*64*PST+b*PST);
            const float4* p2=(const float4*)(phm+b*PST);
            #pragma unroll
            for(int q=0;q<4;++q){
                float4 a=p1[q], h4=p2[q];
                pre[4*q+0]=a.x+h4.x+br[4*q+0];
                pre[4*q+1]=a.y+h4.y+br[4*q+1];
                pre[4*q+2]=a.z+h4.z+br[4*q+2];
                pre[4*q+3]=a.w+h4.w+br[4*q+3];
            }
            float hv0,hv1,hv2,hv3;
            { float f,i2,g2,o2;
              f=fsig(pre[0]);  i2=fsig(pre[1]);  g2=ftanh(pre[2]);  o2=fsig(pre[3]);
              c0=f*c0+i2*g2; hv0=o2*ftanh(c0);
              f=fsig(pre[4]);  i2=fsig(pre[5]);  g2=ftanh(pre[6]);  o2=fsig(pre[7]);
              c1=f*c1+i2*g2; hv1=o2*ftanh(c1);
              f=fsig(pre[8]);  i2=fsig(pre[9]);  g2=ftanh(pre[10]); o2=fsig(pre[11]);
              c2=f*c2+i2*g2; hv2=o2*ftanh(c2);
              f=fsig(pre[12]); i2=fsig(pre[13]); g2=ftanh(pre[14]); o2=fsig(pre[15]);
              c3=f*c3+i2*g2; hv3=o2*ftanh(c3);
            }
            *(float4*)&g_h[par^1][(size_t)b*512+j0]=make_float4(hv0,hv1,hv2,hv3);
            __threadfence();
            barx(4,64);
            if(wid==14&&lane==0) red_rel(&g_ctr);    // release h_t

            stcs4(&out[((size_t)t*BATCH+b)*512+j0], make_float4(hv0,hv1,hv2,hv3));
            if(t==SEQ-1){
                size_t base=(size_t)SEQ*BATCH*512;
                stcs4(&out[base+(size_t)b*512+j0], make_float4(hv0,hv1,hv2,hv3));
                stcs4(&out[base+(size_t)BATCH*512+(size_t)b*512+j0],
                      make_float4(c0,c1,c2,c3));
            }
        }
    }

    // ---- reset persistent state for next graph replay ----
    __syncthreads();
    if(tid==0){
        __threadfence();
        if(atomicAdd(&g_done,1u)==NBLK-1){
            g_done=0u; atomicExch(&g_ctr,0u); __threadfence();
        }
    }
}

extern "C" void kernel_launch(void* const* d_in,const int* in_sizes,int n_in,
                              void* d_out,int out_size)
{
    const float* x =(const float*)d_in[0];
    const float* Wf=(const float*)d_in[1]; const float* bf=(const float*)d_in[2];
    const float* Wi=(const float*)d_in[3]; const float* bi=(const float*)d_in[4];
    const float* Wg=(const float*)d_in[5]; const float* bg=(const float*)d_in[6];
    const float* Wo=(const float*)d_in[7]; const float* bo=(const float*)d_in[8];
    float* out=(float*)d_out;
    cudaFuncSetAttribute(lstm_kernel,cudaFuncAttributeMaxDynamicSharedMemorySize,SMEM_BYTES);
    lstm_kernel<<<NBLK,NTHR,SMEM_BYTES>>>(x,Wf,bf,Wi,bi,Wg,bg,Wo,bo,out);
}